// round 7
// baseline (speedup 1.0000x reference)
#include <cuda_runtime.h>
#include <stdint.h>
#include <math.h>

#define BATCH    256
#define NQ       1000
#define NC       81
#define NELEM    (NQ*NC)     /* 81000 */
#define KTOP     100
#define NT       512
#define NW       (NT/32)     /* 16 warps */
#define CANDBUF  1024
#define TF_ITERS 11
#define BS_ITERS 16
#define FULLM    0xFFFFFFFFu

__device__ __forceinline__ float sigm_precise(float x) { return 1.0f / (1.0f + expf(-x)); }
__device__ __forceinline__ float sigm_fast(float x)    { return __fdividef(1.0f, 1.0f + __expf(-x)); }

__global__ void __launch_bounds__(NT, 2)
postproc_kernel(const float* __restrict__ logits,   // [B,Q,C]
                const float* __restrict__ obj,      // [B,Q]
                const float* __restrict__ boxesIn,  // [B,Q,4]
                const float* __restrict__ unk,      // [B,Q]
                const float* __restrict__ tsz,      // [B,2]
                float* __restrict__ out)
{
    const int b    = blockIdx.x;
    const int tid  = threadIdx.x;
    const int w    = tid >> 5;
    const int lane = tid & 31;

    __shared__ float          fac[NQ];      // exp(-obj)*(1-sig(unk))  (PRECISE)
    __shared__ float          lastv[NQ];    // exp(-obj)*sig(unk)      (PRECISE)
    __shared__ unsigned short qlist[NQ];
    __shared__ unsigned       wc[2][NW * 3];  // double-buffered 3 counts per warp
    __shared__ unsigned       s_cnt, s_nq;
    __shared__ unsigned       cbits[CANDBUF];
    __shared__ unsigned       cidx[CANDBUF];

    // ---- per-query factors (precise; identical formula to verified kernel) ----
    for (int q = tid; q < NQ; q += NT) {
        float o  = obj[b * NQ + q];
        float uu = unk[b * NQ + q];
        float op = expf(-o);
        float su = sigm_precise(uu);
        fac[q]   = op * (1.0f - su);
        lastv[q] = op * su;
    }
    if (tid == 0) { s_cnt = 0; s_nq = 0; }
    __syncthreads();

    const float* L = logits + (size_t)b * NELEM;

    // ---- probe: per-query achieved sample = max(fac*sig(max logit c0..7), lastv) ----
    float smp0 = 0.f, smp1 = 0.f;
    if (tid < NQ) {
        const float* Lq = L + (unsigned)tid * 81u;
        float m = Lq[0];
        #pragma unroll
        for (int c = 1; c < 8; ++c) m = fmaxf(m, Lq[c]);
        smp0 = fmaxf(fac[tid] * sigm_fast(m), lastv[tid]);
    }
    if (tid + NT < NQ) {
        unsigned q = (unsigned)tid + NT;
        const float* Lq = L + q * 81u;
        float m = Lq[0];
        #pragma unroll
        for (int c = 1; c < 8; ++c) m = fmaxf(m, Lq[c]);
        smp1 = fmaxf(fac[q] * sigm_fast(m), lastv[q]);
    }

    // ---- floor select (quaternary, contention-free): Tf ~ 100th achieved sample ----
    unsigned lo = 0u, hi = 0x7F800001u;
    const unsigned sb0 = __float_as_uint(smp0), sb1 = __float_as_uint(smp1);
    for (int it = 0; it < TF_ITERS; ++it) {
        unsigned d  = (hi - lo) >> 2;
        unsigned t1 = lo + d, t2 = lo + 2u * d, t3 = lo + 3u * d;
        unsigned c1 = (unsigned)(sb0 >= t1) + (unsigned)(sb1 >= t1);
        unsigned c2 = (unsigned)(sb0 >= t2) + (unsigned)(sb1 >= t2);
        unsigned c3 = (unsigned)(sb0 >= t3) + (unsigned)(sb1 >= t3);
        c1 = __reduce_add_sync(FULLM, c1);
        c2 = __reduce_add_sync(FULLM, c2);
        c3 = __reduce_add_sync(FULLM, c3);
        unsigned* buf = wc[it & 1];
        if (lane == 0) { buf[w*3+0] = c1; buf[w*3+1] = c2; buf[w*3+2] = c3; }
        __syncthreads();
        unsigned s1 = 0, s2 = 0, s3 = 0;
        #pragma unroll
        for (int k = 0; k < NW; ++k) { s1 += buf[k*3+0]; s2 += buf[k*3+1]; s3 += buf[k*3+2]; }
        if      (s3 >= KTOP) lo = t3;
        else if (s2 >= KTOP) { lo = t2; hi = t3; }
        else if (s1 >= KTOP) { lo = t1; hi = t2; }
        else                 hi = t1;
    }
    const float Tq = __uint_as_float(lo) * 0.99997f;   // query-prune threshold

    // ---- survivor-query compaction (ballot-aggregated; pruned queries never loaded) ----
    for (int qb = 0; qb < NQ; qb += NT) {
        int q = qb + tid;
        bool p = (q < NQ) && (fac[q] >= Tq);
        unsigned m = __ballot_sync(FULLM, p);
        unsigned base = 0;
        if (lane == 0 && m) base = atomicAdd(&s_nq, (unsigned)__popc(m));
        base = __shfl_sync(FULLM, base, 0);
        if (p) qlist[base + __popc(m & ((1u << lane) - 1u))] = (unsigned short)q;
    }
    __syncthreads();
    const unsigned nq = s_nq;

    // ---- scan survivors: half-warp (16 lanes) per query, per-lane top-4 ----
    unsigned b0 = 0, b1 = 0, b2 = 0, b3 = 0;
    unsigned i0 = 0xFFFFFFFFu, i1 = 0xFFFFFFFFu, i2 = 0xFFFFFFFFu, i3 = 0xFFFFFFFFu;
    const unsigned hw = (unsigned)tid >> 4, j = (unsigned)tid & 15u;

    for (unsigned s = hw; s < nq; s += NT / 16) {
        unsigned q = qlist[s];
        float f = fac[q];
        const float* Lq = L + q * 81u;
        #pragma unroll
        for (int k = 0; k < 4; ++k) {
            unsigned c = j + 16u * (unsigned)k;
            if (c < 60u) {
                float p = f * sigm_fast(Lq[c]);
                unsigned pb = __float_as_uint(p);
                if (pb > b3) {
                    unsigned ee = q * 81u + c;
                    if (pb > b1) {
                        if (pb > b0) { b3=b2;i3=i2; b2=b1;i2=i1; b1=b0;i1=i0; b0=pb;i0=ee; }
                        else         { b3=b2;i3=i2; b2=b1;i2=i1; b1=pb;i1=ee; }
                    } else {
                        if (pb > b2) { b3=b2;i3=i2; b2=pb;i2=ee; }
                        else         { b3=pb;i3=ee; }
                    }
                }
            }
        }
    }
    __syncthreads();

    // ---- main select (quaternary) over kept top-4s + ALL lastv: tight T_keep ----
    unsigned lb0 = (tid < NQ)      ? __float_as_uint(lastv[tid])      : 0u;
    unsigned lb1 = (tid + NT < NQ) ? __float_as_uint(lastv[tid + NT]) : 0u;
    lo = 0u; hi = 0x7F800001u;
    for (int it = 0; it < BS_ITERS; ++it) {
        unsigned d  = (hi - lo) >> 2;
        unsigned t1 = lo + d, t2 = lo + 2u * d, t3 = lo + 3u * d;
        unsigned c1 = (unsigned)(b0>=t1)+(unsigned)(b1>=t1)+(unsigned)(b2>=t1)
                    + (unsigned)(b3>=t1)+(unsigned)(lb0>=t1)+(unsigned)(lb1>=t1);
        unsigned c2 = (unsigned)(b0>=t2)+(unsigned)(b1>=t2)+(unsigned)(b2>=t2)
                    + (unsigned)(b3>=t2)+(unsigned)(lb0>=t2)+(unsigned)(lb1>=t2);
        unsigned c3 = (unsigned)(b0>=t3)+(unsigned)(b1>=t3)+(unsigned)(b2>=t3)
                    + (unsigned)(b3>=t3)+(unsigned)(lb0>=t3)+(unsigned)(lb1>=t3);
        c1 = __reduce_add_sync(FULLM, c1);
        c2 = __reduce_add_sync(FULLM, c2);
        c3 = __reduce_add_sync(FULLM, c3);
        unsigned* buf = wc[it & 1];
        if (lane == 0) { buf[w*3+0] = c1; buf[w*3+1] = c2; buf[w*3+2] = c3; }
        __syncthreads();
        unsigned s1 = 0, s2 = 0, s3 = 0;
        #pragma unroll
        for (int k = 0; k < NW; ++k) { s1 += buf[k*3+0]; s2 += buf[k*3+1]; s3 += buf[k*3+2]; }
        if      (s3 >= KTOP) lo = t3;
        else if (s2 >= KTOP) { lo = t2; hi = t3; }
        else if (s1 >= KTOP) { lo = t1; hi = t2; }
        else                 hi = t1;
    }
    unsigned T_keep = 0u;
    if (lo != 0u) T_keep = __float_as_uint(__uint_as_float(lo) * 0.99998f);

    // ---- collect candidates (ballot-aggregated): provable superset of top-100 ----
    {
        bool pr; unsigned m, base, pos;
        #define PUSH(P, IDX)                                                          \
            pr = (P);                                                                 \
            m = __ballot_sync(FULLM, pr);                                             \
            base = 0;                                                                 \
            if (lane == 0 && m) base = atomicAdd(&s_cnt, (unsigned)__popc(m));        \
            base = __shfl_sync(FULLM, base, 0);                                       \
            if (pr) { pos = base + __popc(m & ((1u << lane) - 1u));                   \
                      if (pos < CANDBUF) cidx[pos] = (IDX); }
        PUSH(b0 >= T_keep && i0 != 0xFFFFFFFFu, i0)
        PUSH(b1 >= T_keep && i1 != 0xFFFFFFFFu, i1)
        PUSH(b2 >= T_keep && i2 != 0xFFFFFFFFu, i2)
        PUSH(b3 >= T_keep && i3 != 0xFFFFFFFFu, i3)
        PUSH(lb0 >= T_keep && tid < NQ,      (unsigned)tid * 81u + 80u)
        PUSH(lb1 >= T_keep && tid + NT < NQ, ((unsigned)tid + NT) * 81u + 80u)
        #undef PUSH
    }

    if (b3 >= T_keep) {
        // this lane may have dropped qualifiers: rescan ONLY its own queries (cache-hot)
        for (unsigned s = hw; s < nq; s += NT / 16) {
            unsigned q = qlist[s];
            float f = fac[q];
            const float* Lq = L + q * 81u;
            #pragma unroll
            for (int k = 0; k < 4; ++k) {
                unsigned c = j + 16u * (unsigned)k;
                if (c < 60u) {
                    float p = f * sigm_fast(Lq[c]);
                    unsigned pb = __float_as_uint(p);
                    unsigned ee = q * 81u + c;
                    if (pb >= T_keep && ee != i0 && ee != i1 && ee != i2 && ee != i3) {
                        unsigned pos = atomicAdd(&s_cnt, 1u);
                        if (pos < CANDBUF) cidx[pos] = ee;
                    }
                }
            }
        }
    }
    __syncthreads();
    const unsigned nF = (s_cnt < CANDBUF) ? s_cnt : CANDBUF;

    // ---- recompute candidates PRECISELY (bit-identical to verified formula) ----
    for (unsigned i = tid; i < nF; i += NT) {
        unsigned e = cidx[i];
        unsigned q = e / 81u;
        unsigned c = e - q * 81u;
        float p = (c < 60u) ? fac[q] * sigm_precise(L[e]) : lastv[q];
        cbits[i] = __float_as_uint(p);
    }
    __syncthreads();

    // ---- exact rank ordering (precise value desc, index asc) and output ----
    const float* Bx = boxesIn + (size_t)b * NQ * 4;
    const float ih = tsz[b * 2 + 0];
    const float iw = tsz[b * 2 + 1];

    for (unsigned i = tid; i < nF; i += NT) {
        unsigned bi = cbits[i], xi = cidx[i];
        unsigned r = 0;
        for (unsigned jj = 0; jj < nF; jj++) {
            unsigned bj = cbits[jj], xj = cidx[jj];
            r += (bj > bi) || (bj == bi && xj < xi);
        }
        if (r < KTOP) {
            unsigned q = xi / 81u;
            unsigned c = xi - q * 81u;
            out[(size_t)b * KTOP + r]                        = __uint_as_float(bi);
            out[(size_t)BATCH * KTOP + (size_t)b * KTOP + r] = (float)c;
            float cx = Bx[q * 4 + 0], cy = Bx[q * 4 + 1];
            float ww = Bx[q * 4 + 2], hh = Bx[q * 4 + 3];
            float* ob = out + (size_t)2 * BATCH * KTOP + ((size_t)b * KTOP + r) * 4;
            ob[0] = (cx - 0.5f * ww) * iw;
            ob[1] = (cy - 0.5f * hh) * ih;
            ob[2] = (cx + 0.5f * ww) * iw;
            ob[3] = (cy + 0.5f * hh) * ih;
        }
    }
}

extern "C" void kernel_launch(void* const* d_in, const int* in_sizes, int n_in,
                              void* d_out, int out_size)
{
    const float* logits  = (const float*)d_in[0];  // (256,1000,81)
    const float* obj     = (const float*)d_in[1];  // (256,1000)
    const float* boxesIn = (const float*)d_in[2];  // (256,1000,4)
    const float* unk     = (const float*)d_in[3];  // (256,1000)
    const float* tsz     = (const float*)d_in[4];  // (256,2)
    float* out = (float*)d_out;
    (void)in_sizes; (void)n_in; (void)out_size;

    postproc_kernel<<<BATCH, NT>>>(logits, obj, boxesIn, unk, tsz, out);
}

// round 8
// speedup vs baseline: 1.5588x; 1.5588x over previous
#include <cuda_runtime.h>
#include <stdint.h>
#include <math.h>

#define BATCH    256
#define NQ       1000
#define NC       81
#define NELEM    (NQ*NC)     /* 81000 */
#define KTOP     100
#define NT       512
#define NW       (NT/32)     /* 16 warps */
#define CANDBUF  1024
#define NBIN1    2048
#define NBIN2    256
#define FULLM    0xFFFFFFFFu

__device__ __forceinline__ float sigm_precise(float x) { return 1.0f / (1.0f + expf(-x)); }
__device__ __forceinline__ float sigm_fast(float x)    { return __fdividef(1.0f, 1.0f + __expf(-x)); }

__global__ void __launch_bounds__(NT, 2)
postproc_kernel(const float* __restrict__ logits,   // [B,Q,C]
                const float* __restrict__ obj,      // [B,Q]
                const float* __restrict__ boxesIn,  // [B,Q,4]
                const float* __restrict__ unk,      // [B,Q]
                const float* __restrict__ tsz,      // [B,2]
                float* __restrict__ out)
{
    const int b    = blockIdx.x;
    const int tid  = threadIdx.x;
    const int lane = tid & 31;
    const int w    = tid >> 5;

    __shared__ float          fac[NQ];      // exp(-obj)*(1-sig(unk))  (PRECISE)
    __shared__ float          lastv[NQ];    // exp(-obj)*sig(unk)      (PRECISE)
    __shared__ unsigned short qlist[NQ];
    __shared__ unsigned       hist[NBIN1];
    __shared__ int            s_t1;
    __shared__ unsigned       s_carry, s_T;
    __shared__ unsigned       s_cnt, s_nq;
    __shared__ unsigned       cbits[CANDBUF];
    __shared__ unsigned       cidx[CANDBUF];

    // ---- per-query factors (precise; identical formula to verified kernel) ----
    for (int q = tid; q < NQ; q += NT) {
        float o  = obj[b * NQ + q];
        float uu = unk[b * NQ + q];
        float op = expf(-o);
        float su = sigm_precise(uu);
        fac[q]   = op * (1.0f - su);
        lastv[q] = op * su;
    }
    if (tid == 0) { s_cnt = 0; s_nq = 0; }
    __syncthreads();

    const float* L = logits + (size_t)b * NELEM;

    // ---- probe: per-query achieved sample = max(fac*sig(max logit c0..7), lastv) ----
    float smp0 = 0.f, smp1 = 0.f;
    if (tid < NQ) {
        const float* Lq = L + (unsigned)tid * 81u;
        float m = Lq[0];
        #pragma unroll
        for (int c = 1; c < 8; ++c) m = fmaxf(m, Lq[c]);
        smp0 = fmaxf(fac[tid] * sigm_fast(m), lastv[tid]);
    }
    if (tid + NT < NQ) {
        unsigned q = (unsigned)tid + NT;
        const float* Lq = L + q * 81u;
        float m = Lq[0];
        #pragma unroll
        for (int c = 1; c < 8; ++c) m = fmaxf(m, Lq[c]);
        smp1 = fmaxf(fac[q] * sigm_fast(m), lastv[q]);
    }
    const unsigned sb0 = __float_as_uint(smp0), sb1 = __float_as_uint(smp1);

    // ============== histogram select #1: floor Tq from 2000 achieved samples ==============
    for (int i = tid; i < NBIN1; i += NT) hist[i] = 0;
    __syncthreads();
    if (sb0) atomicAdd(&hist[sb0 >> 20], 1u);
    if (sb1) atomicAdd(&hist[sb1 >> 20], 1u);
    __syncthreads();
    if (w == 0) {
        unsigned csum = 0;
        for (int k = 0; k < NBIN1 / 32; ++k) csum += hist[lane * (NBIN1 / 32) + k];
        unsigned s = csum;
        #pragma unroll
        for (int off = 1; off < 32; off <<= 1) {
            unsigned v = __shfl_down_sync(FULLM, s, off);
            if (lane + off < 32) s += v;
        }
        unsigned snext = __shfl_down_sync(FULLM, s, 1);
        if (lane == 31) snext = 0;
        if (lane == 0 && s < KTOP) s_t1 = -1;
        if (s >= KTOP && snext < KTOP) {
            unsigned acc = snext; int t = 0; unsigned carry = 0;
            for (int kk = NBIN1 / 32 - 1; kk >= 0; --kk) {
                unsigned h = hist[lane * (NBIN1 / 32) + kk];
                if (acc + h >= KTOP) { t = lane * (NBIN1 / 32) + kk; carry = acc; break; }
                acc += h;
            }
            s_t1 = t; s_carry = carry;
        }
    }
    __syncthreads();
    float Tq = 0.0f;
    {
        int t1 = s_t1;
        if (t1 >= 0) {
            if (tid < NBIN2) hist[tid] = 0;
            __syncthreads();
            if ((int)(sb0 >> 20) == t1) atomicAdd(&hist[(sb0 >> 12) & 255u], 1u);
            if ((int)(sb1 >> 20) == t1) atomicAdd(&hist[(sb1 >> 12) & 255u], 1u);
            __syncthreads();
            if (w == 0) {
                unsigned K2 = KTOP - s_carry;
                unsigned csum = 0;
                for (int k = 0; k < NBIN2 / 32; ++k) csum += hist[lane * (NBIN2 / 32) + k];
                unsigned s = csum;
                #pragma unroll
                for (int off = 1; off < 32; off <<= 1) {
                    unsigned v = __shfl_down_sync(FULLM, s, off);
                    if (lane + off < 32) s += v;
                }
                unsigned snext = __shfl_down_sync(FULLM, s, 1);
                if (lane == 31) snext = 0;
                if (s >= K2 && snext < K2) {
                    unsigned acc = snext; int t2 = 0;
                    for (int kk = NBIN2 / 32 - 1; kk >= 0; --kk) {
                        unsigned h = hist[lane * (NBIN2 / 32) + kk];
                        if (acc + h >= K2) { t2 = lane * (NBIN2 / 32) + kk; break; }
                        acc += h;
                    }
                    s_T = ((unsigned)t1 << 20) | ((unsigned)t2 << 12);
                }
            }
            __syncthreads();
            Tq = __uint_as_float(s_T) * 0.99997f;   // query-prune threshold (valid floor w/ margin)
        }
    }

    // ---- survivor-query compaction (ballot-aggregated; pruned queries never loaded) ----
    for (int qb = 0; qb < NQ; qb += NT) {
        int q = qb + tid;
        bool p = (q < NQ) && (fac[q] >= Tq);
        unsigned m = __ballot_sync(FULLM, p);
        unsigned base = 0;
        if (lane == 0 && m) base = atomicAdd(&s_nq, (unsigned)__popc(m));
        base = __shfl_sync(FULLM, base, 0);
        if (p) qlist[base + __popc(m & ((1u << lane) - 1u))] = (unsigned short)q;
    }
    __syncthreads();
    const unsigned nq = s_nq;

    // ---- scan survivors: half-warp (16 lanes) per query, per-lane top-4 ----
    unsigned b0 = 0, b1 = 0, b2 = 0, b3 = 0;
    unsigned i0 = 0xFFFFFFFFu, i1 = 0xFFFFFFFFu, i2 = 0xFFFFFFFFu, i3 = 0xFFFFFFFFu;
    const unsigned hw = (unsigned)tid >> 4, j = (unsigned)tid & 15u;

    for (unsigned s = hw; s < nq; s += NT / 16) {
        unsigned q = qlist[s];
        float f = fac[q];
        const float* Lq = L + q * 81u;
        #pragma unroll
        for (int k = 0; k < 4; ++k) {
            unsigned c = j + 16u * (unsigned)k;
            if (c < 60u) {
                float p = f * sigm_fast(Lq[c]);
                unsigned pb = __float_as_uint(p);
                if (pb > b3) {
                    unsigned ee = q * 81u + c;
                    if (pb > b1) {
                        if (pb > b0) { b3=b2;i3=i2; b2=b1;i2=i1; b1=b0;i1=i0; b0=pb;i0=ee; }
                        else         { b3=b2;i3=i2; b2=b1;i2=i1; b1=pb;i1=ee; }
                    } else {
                        if (pb > b2) { b3=b2;i3=i2; b2=pb;i2=ee; }
                        else         { b3=pb;i3=ee; }
                    }
                }
            }
        }
    }
    const unsigned lb0 = (tid < NQ)      ? __float_as_uint(lastv[tid])      : 0u;
    const unsigned lb1 = (tid + NT < NQ) ? __float_as_uint(lastv[tid + NT]) : 0u;
    __syncthreads();

    // ============== histogram select #2: tight T_keep over kept top-4s + lastv ==============
    for (int i = tid; i < NBIN1; i += NT) hist[i] = 0;
    __syncthreads();
    if (b0)  atomicAdd(&hist[b0  >> 20], 1u);
    if (b1)  atomicAdd(&hist[b1  >> 20], 1u);
    if (b2)  atomicAdd(&hist[b2  >> 20], 1u);
    if (b3)  atomicAdd(&hist[b3  >> 20], 1u);
    if (lb0) atomicAdd(&hist[lb0 >> 20], 1u);
    if (lb1) atomicAdd(&hist[lb1 >> 20], 1u);
    __syncthreads();
    if (w == 0) {
        unsigned csum = 0;
        for (int k = 0; k < NBIN1 / 32; ++k) csum += hist[lane * (NBIN1 / 32) + k];
        unsigned s = csum;
        #pragma unroll
        for (int off = 1; off < 32; off <<= 1) {
            unsigned v = __shfl_down_sync(FULLM, s, off);
            if (lane + off < 32) s += v;
        }
        unsigned snext = __shfl_down_sync(FULLM, s, 1);
        if (lane == 31) snext = 0;
        if (lane == 0 && s < KTOP) s_t1 = -1;
        if (s >= KTOP && snext < KTOP) {
            unsigned acc = snext; int t = 0; unsigned carry = 0;
            for (int kk = NBIN1 / 32 - 1; kk >= 0; --kk) {
                unsigned h = hist[lane * (NBIN1 / 32) + kk];
                if (acc + h >= KTOP) { t = lane * (NBIN1 / 32) + kk; carry = acc; break; }
                acc += h;
            }
            s_t1 = t; s_carry = carry;
        }
    }
    __syncthreads();
    unsigned T_keep = 0u;
    {
        int t1 = s_t1;
        if (t1 >= 0) {
            if (tid < NBIN2) hist[tid] = 0;
            __syncthreads();
            if ((int)(b0  >> 20) == t1) atomicAdd(&hist[(b0  >> 12) & 255u], 1u);
            if ((int)(b1  >> 20) == t1) atomicAdd(&hist[(b1  >> 12) & 255u], 1u);
            if ((int)(b2  >> 20) == t1) atomicAdd(&hist[(b2  >> 12) & 255u], 1u);
            if ((int)(b3  >> 20) == t1) atomicAdd(&hist[(b3  >> 12) & 255u], 1u);
            if ((int)(lb0 >> 20) == t1) atomicAdd(&hist[(lb0 >> 12) & 255u], 1u);
            if ((int)(lb1 >> 20) == t1) atomicAdd(&hist[(lb1 >> 12) & 255u], 1u);
            __syncthreads();
            if (w == 0) {
                unsigned K2 = KTOP - s_carry;
                unsigned csum = 0;
                for (int k = 0; k < NBIN2 / 32; ++k) csum += hist[lane * (NBIN2 / 32) + k];
                unsigned s = csum;
                #pragma unroll
                for (int off = 1; off < 32; off <<= 1) {
                    unsigned v = __shfl_down_sync(FULLM, s, off);
                    if (lane + off < 32) s += v;
                }
                unsigned snext = __shfl_down_sync(FULLM, s, 1);
                if (lane == 31) snext = 0;
                if (s >= K2 && snext < K2) {
                    unsigned acc = snext; int t2 = 0;
                    for (int kk = NBIN2 / 32 - 1; kk >= 0; --kk) {
                        unsigned h = hist[lane * (NBIN2 / 32) + kk];
                        if (acc + h >= K2) { t2 = lane * (NBIN2 / 32) + kk; break; }
                        acc += h;
                    }
                    s_T = ((unsigned)t1 << 20) | ((unsigned)t2 << 12);
                }
            }
            __syncthreads();
            unsigned Tb = s_T;
            if (Tb != 0u) T_keep = __float_as_uint(__uint_as_float(Tb) * 0.99998f);
        }
    }

    // ---- collect candidates (ballot-aggregated): provable superset of top-100 ----
    {
        bool pr; unsigned m, base, pos;
        #define PUSH(P, IDX)                                                          \
            pr = (P);                                                                 \
            m = __ballot_sync(FULLM, pr);                                             \
            base = 0;                                                                 \
            if (lane == 0 && m) base = atomicAdd(&s_cnt, (unsigned)__popc(m));        \
            base = __shfl_sync(FULLM, base, 0);                                       \
            if (pr) { pos = base + __popc(m & ((1u << lane) - 1u));                   \
                      if (pos < CANDBUF) cidx[pos] = (IDX); }
        PUSH(b0 >= T_keep && i0 != 0xFFFFFFFFu, i0)
        PUSH(b1 >= T_keep && i1 != 0xFFFFFFFFu, i1)
        PUSH(b2 >= T_keep && i2 != 0xFFFFFFFFu, i2)
        PUSH(b3 >= T_keep && i3 != 0xFFFFFFFFu, i3)
        PUSH(lb0 >= T_keep && tid < NQ,      (unsigned)tid * 81u + 80u)
        PUSH(lb1 >= T_keep && tid + NT < NQ, ((unsigned)tid + NT) * 81u + 80u)
        #undef PUSH
    }

    if (b3 >= T_keep) {
        // this lane may have dropped qualifiers: rescan ONLY its own queries (cache-hot)
        for (unsigned s = hw; s < nq; s += NT / 16) {
            unsigned q = qlist[s];
            float f = fac[q];
            const float* Lq = L + q * 81u;
            #pragma unroll
            for (int k = 0; k < 4; ++k) {
                unsigned c = j + 16u * (unsigned)k;
                if (c < 60u) {
                    float p = f * sigm_fast(Lq[c]);
                    unsigned pb = __float_as_uint(p);
                    unsigned ee = q * 81u + c;
                    if (pb >= T_keep && ee != i0 && ee != i1 && ee != i2 && ee != i3) {
                        unsigned pos = atomicAdd(&s_cnt, 1u);
                        if (pos < CANDBUF) cidx[pos] = ee;
                    }
                }
            }
        }
    }
    __syncthreads();
    const unsigned nF = (s_cnt < CANDBUF) ? s_cnt : CANDBUF;

    // ---- recompute candidates PRECISELY (bit-identical to verified formula) ----
    for (unsigned i = tid; i < nF; i += NT) {
        unsigned e = cidx[i];
        unsigned q = e / 81u;
        unsigned c = e - q * 81u;
        float p = (c < 60u) ? fac[q] * sigm_precise(L[e]) : lastv[q];
        cbits[i] = __float_as_uint(p);
    }
    __syncthreads();

    // ---- exact rank ordering (precise value desc, index asc) and output ----
    const float* Bx = boxesIn + (size_t)b * NQ * 4;
    const float ih = tsz[b * 2 + 0];
    const float iw = tsz[b * 2 + 1];

    for (unsigned i = tid; i < nF; i += NT) {
        unsigned bi = cbits[i], xi = cidx[i];
        unsigned r = 0;
        for (unsigned jj = 0; jj < nF; jj++) {
            unsigned bj = cbits[jj], xj = cidx[jj];
            r += (bj > bi) || (bj == bi && xj < xi);
        }
        if (r < KTOP) {
            unsigned q = xi / 81u;
            unsigned c = xi - q * 81u;
            out[(size_t)b * KTOP + r]                        = __uint_as_float(bi);
            out[(size_t)BATCH * KTOP + (size_t)b * KTOP + r] = (float)c;
            float cx = Bx[q * 4 + 0], cy = Bx[q * 4 + 1];
            float ww = Bx[q * 4 + 2], hh = Bx[q * 4 + 3];
            float* ob = out + (size_t)2 * BATCH * KTOP + ((size_t)b * KTOP + r) * 4;
            ob[0] = (cx - 0.5f * ww) * iw;
            ob[1] = (cy - 0.5f * hh) * ih;
            ob[2] = (cx + 0.5f * ww) * iw;
            ob[3] = (cy + 0.5f * hh) * ih;
        }
    }
}

extern "C" void kernel_launch(void* const* d_in, const int* in_sizes, int n_in,
                              void* d_out, int out_size)
{
    const float* logits  = (const float*)d_in[0];  // (256,1000,81)
    const float* obj     = (const float*)d_in[1];  // (256,1000)
    const float* boxesIn = (const float*)d_in[2];  // (256,1000,4)
    const float* unk     = (const float*)d_in[3];  // (256,1000)
    const float* tsz     = (const float*)d_in[4];  // (256,2)
    float* out = (float*)d_out;
    (void)in_sizes; (void)n_in; (void)out_size;

    postproc_kernel<<<BATCH, NT>>>(logits, obj, boxesIn, unk, tsz, out);
}